// round 1
// baseline (speedup 1.0000x reference)
#include <cuda_runtime.h>
#include <cstdint>

// Problem constants
#define B_    8
#define N_    1024
#define FIN   256
#define NH    8
#define ND    32
#define M_TOT (B_ * N_)      // 8192
#define NBH   (B_ * NH)      // 64
#define ROWS  1025           // prefix/suffix rows: t in [0,1024]
#define OCOLS (NH * ND)      // 256

// ---------------- scratch (no allocations allowed) ----------------
__device__ float g_buf[M_TOT * OCOLS];        // 8 MB: g[b,n,h,d] row-major (m, h*32+d)
__device__ float ssrc_buf[M_TOT * NH];
__device__ float sdst_buf[M_TOT * NH];
__device__ float vsort_buf[NBH * N_];         // sorted dst values per (b,h)
__device__ float suf1_buf[NBH * ROWS * ND];   // SUF1[t][d] = sum_{k>=t} exp(v_k) g[pi_k][d]
__device__ float pre2_buf[NBH * ROWS * ND];   // PRE2[t][d] = sum_{k< t} exp(.2 v_k) g[pi_k][d]
__device__ float c1_buf[NBH * ROWS];          // scalar suffix of exp(v_k)
__device__ float c2_buf[NBH * ROWS];          // scalar prefix of exp(.2 v_k)

// ---------------- kernel 1: g = vertex @ w_vert (fp32 tiled GEMM) ----------------
// M=8192, K=256, N=256. BM=BN=64, BK=16, 256 threads, 4x4 microtile.
__global__ __launch_bounds__(256) void gemm_g_k(const float* __restrict__ A,
                                                const float* __restrict__ Bw) {
    __shared__ float As[16][64];   // [k][row]
    __shared__ float Bs[16][64];   // [k][col]
    int tid = threadIdx.x;
    int tx = tid & 15;             // col group (4 cols)
    int ty = tid >> 4;             // row group (4 rows)
    int rowBase = blockIdx.y * 64;
    int colBase = blockIdx.x * 64;

    int aRow = tid >> 2;           // 0..63
    int aCol = (tid & 3) << 2;     // 0,4,8,12
    int bRow = tid >> 4;           // 0..15
    int bCol = (tid & 15) << 2;    // 0..60

    float acc[4][4];
#pragma unroll
    for (int m = 0; m < 4; m++)
#pragma unroll
        for (int n = 0; n < 4; n++) acc[m][n] = 0.f;

    for (int k0 = 0; k0 < FIN; k0 += 16) {
        float4 av = *(const float4*)(A + (size_t)(rowBase + aRow) * FIN + k0 + aCol);
        As[aCol + 0][aRow] = av.x;
        As[aCol + 1][aRow] = av.y;
        As[aCol + 2][aRow] = av.z;
        As[aCol + 3][aRow] = av.w;
        float4 bv = *(const float4*)(Bw + (size_t)(k0 + bRow) * OCOLS + colBase + bCol);
        *(float4*)&Bs[bRow][bCol] = bv;
        __syncthreads();
#pragma unroll
        for (int k = 0; k < 16; k++) {
            float4 a4 = *(const float4*)&As[k][ty << 2];
            float4 b4 = *(const float4*)&Bs[k][tx << 2];
            float a[4] = {a4.x, a4.y, a4.z, a4.w};
            float b[4] = {b4.x, b4.y, b4.z, b4.w};
#pragma unroll
            for (int m = 0; m < 4; m++)
#pragma unroll
                for (int n = 0; n < 4; n++) acc[m][n] += a[m] * b[n];
        }
        __syncthreads();
    }
#pragma unroll
    for (int m = 0; m < 4; m++) {
        float4 o = make_float4(acc[m][0], acc[m][1], acc[m][2], acc[m][3]);
        *(float4*)(g_buf + (size_t)(rowBase + (ty << 2) + m) * OCOLS + colBase + (tx << 2)) = o;
    }
}

// ---------------- kernel 2: s_src, s_dst ----------------
__global__ __launch_bounds__(256) void score_k(const float* __restrict__ attn_w) {
    int w = threadIdx.x >> 5, lane = threadIdx.x & 31;
    int m = blockIdx.x * 8 + w;          // 1024 blocks * 8 warps = 8192
    float ws = attn_w[lane];
    float wd = attn_w[32 + lane];
    const float* gr = g_buf + (size_t)m * OCOLS;
#pragma unroll
    for (int h = 0; h < NH; h++) {
        float gv = gr[h * ND + lane];
        float a = gv * ws, b = gv * wd;
#pragma unroll
        for (int o = 16; o > 0; o >>= 1) {
            a += __shfl_xor_sync(0xffffffffu, a, o);
            b += __shfl_xor_sync(0xffffffffu, b, o);
        }
        if (lane == 0) {
            ssrc_buf[m * NH + h] = a;
            sdst_buf[m * NH + h] = b;
        }
    }
}

// ---------------- kernel 3: per-(b,h) sort + prefix/suffix structures ----------------
// 64 blocks x 1024 threads.
__global__ __launch_bounds__(1024) void prep_k() {
    __shared__ float v[1024];
    __shared__ int   id[1024];
    __shared__ float ew1[1024];
    __shared__ float ew2[1024];
    __shared__ float sc[1024];
    __shared__ float tot1[32][33];
    __shared__ float tot2[32][33];

    int bh = blockIdx.x;
    int b = bh >> 3, h = bh & 7;
    int tid = threadIdx.x;
    int w = tid >> 5, lane = tid & 31;

    v[tid] = sdst_buf[(size_t)(b * N_ + tid) * NH + h];
    id[tid] = tid;
    __syncthreads();

    // bitonic sort ascending (key v, payload id)
    for (int k = 2; k <= 1024; k <<= 1) {
        for (int j = k >> 1; j > 0; j >>= 1) {
            int ixj = tid ^ j;
            if (ixj > tid) {
                bool up = ((tid & k) == 0);
                float a = v[tid], c = v[ixj];
                bool swap = up ? (a > c) : (a < c);
                if (swap) {
                    v[tid] = c; v[ixj] = a;
                    int t_ = id[tid]; id[tid] = id[ixj]; id[ixj] = t_;
                }
            }
            __syncthreads();
        }
    }

    ew1[tid] = __expf(v[tid]);
    ew2[tid] = __expf(0.2f * v[tid]);
    vsort_buf[(size_t)bh * N_ + tid] = v[tid];
    __syncthreads();

    // scalar prefix (ew2) -> c2, scalar suffix (ew1) -> c1 (Hillis-Steele)
    sc[tid] = ew2[tid];
    __syncthreads();
    for (int off = 1; off < 1024; off <<= 1) {
        float x = sc[tid] + ((tid >= off) ? sc[tid - off] : 0.f);
        __syncthreads();
        sc[tid] = x;
        __syncthreads();
    }
    c2_buf[(size_t)bh * ROWS + tid + 1] = sc[tid];
    if (tid == 0) c2_buf[(size_t)bh * ROWS] = 0.f;
    __syncthreads();

    sc[tid] = ew1[tid];
    __syncthreads();
    for (int off = 1; off < 1024; off <<= 1) {
        float x = sc[tid] + ((tid + off < 1024) ? sc[tid + off] : 0.f);
        __syncthreads();
        sc[tid] = x;
        __syncthreads();
    }
    c1_buf[(size_t)bh * ROWS + tid] = sc[tid];
    if (tid == 0) c1_buf[(size_t)bh * ROWS + 1024] = 0.f;
    __syncthreads();

    // vector passes: warp w owns k in [w*32, w*32+32), lane = d
    const float* gb = g_buf + (size_t)b * N_ * OCOLS + h * ND;

    // pass 1: warp-chunk totals
    float t1 = 0.f, t2 = 0.f;
    for (int kk = 0; kk < 32; kk++) {
        int k = (w << 5) + kk;
        int j = id[k];
        float gv = gb[(size_t)j * OCOLS + lane];
        t1 += ew1[k] * gv;
        t2 += ew2[k] * gv;
    }
    tot1[w][lane] = t1;
    tot2[w][lane] = t2;
    __syncthreads();

    // cross-warp scans: warp w scans dim d=w over warp-index axis.
    {
        float x1 = tot1[lane][w];
        float x2 = tot2[lane][w];
        // exclusive suffix scan of x1 (sum over warps > lane)
        float inc1 = x1;
#pragma unroll
        for (int o = 1; o < 32; o <<= 1) {
            float y = __shfl_down_sync(0xffffffffu, inc1, o);
            if (lane + o < 32) inc1 += y;
        }
        // exclusive prefix scan of x2 (sum over warps < lane)
        float inc2 = x2;
#pragma unroll
        for (int o = 1; o < 32; o <<= 1) {
            float y = __shfl_up_sync(0xffffffffu, inc2, o);
            if (lane >= o) inc2 += y;
        }
        tot1[lane][w] = inc1 - x1;
        tot2[lane][w] = inc2 - x2;
    }
    __syncthreads();

    // pass 2: prefix write of ew2*g -> PRE2[k+1]
    {
        float r2 = tot2[w][lane];
        float* P2 = pre2_buf + (size_t)bh * ROWS * ND;
        for (int kk = 0; kk < 32; kk++) {
            int k = (w << 5) + kk;
            int j = id[k];
            float gv = gb[(size_t)j * OCOLS + lane];
            r2 += ew2[k] * gv;
            P2[(size_t)(k + 1) * ND + lane] = r2;
        }
        if (tid < 32) P2[lane] = 0.f;   // PRE2[0] = 0
    }
    // pass 3: suffix write of ew1*g -> SUF1[k]
    {
        float r1 = tot1[w][lane];
        float* S1 = suf1_buf + (size_t)bh * ROWS * ND;
        for (int kk = 31; kk >= 0; kk--) {
            int k = (w << 5) + kk;
            int j = id[k];
            float gv = gb[(size_t)j * OCOLS + lane];
            r1 += ew1[k] * gv;
            S1[(size_t)k * ND + lane] = r1;
        }
        if (tid < 32) S1[(size_t)1024 * ND + lane] = 0.f;  // SUF1[1024] = 0
    }
}

// ---------------- kernel 4: per-query output ----------------
// 2048 blocks x 1024 threads; block = (bh, chunk of 32 queries), warp = query, lane = d.
__global__ __launch_bounds__(1024) void query_k(float* __restrict__ out) {
    __shared__ float vs[1024];
    int bh = blockIdx.x >> 5;
    int chunk = blockIdx.x & 31;
    int b = bh >> 3, h = bh & 7;
    int tid = threadIdx.x, w = tid >> 5, lane = tid & 31;

    vs[tid] = vsort_buf[(size_t)bh * N_ + tid];
    __syncthreads();

    int i = (chunk << 5) + w;
    int m = b * N_ + i;
    float src = ssrc_buf[(size_t)m * NH + h];
    float th = -src;

    // lower_bound: first t with vs[t] >= th  (warp-uniform)
    int lo = 0, hi = 1024;
#pragma unroll
    for (int s = 0; s < 10; s++) {
        int mid = (lo + hi) >> 1;
        if (vs[mid] < th) lo = mid + 1; else hi = mid;
    }
    int t = lo;

    float vmax = vs[1023];
    float etop = src + vmax;
    float mM = (etop >= 0.f) ? etop : 0.2f * etop;  // max_j e_ij (monotone leaky)
    float E1 = (t < 1024) ? __expf(src - mM) : 0.f;
    float E2 = (t > 0)    ? __expf(0.2f * src - mM) : 0.f;

    float cs = c1_buf[(size_t)bh * ROWS + t];   // sum_{k>=t} exp(v_k)
    float cp = c2_buf[(size_t)bh * ROWS + t];   // sum_{k< t} exp(.2 v_k)
    float den = E1 * cs + E2 * cp;

    size_t base = ((size_t)bh * ROWS + t) * ND + lane;
    float num = E1 * suf1_buf[base] + E2 * pre2_buf[base];

    out[(size_t)m * OCOLS + h * ND + lane] = num / den;
}

// ---------------- launcher ----------------
extern "C" void kernel_launch(void* const* d_in, const int* in_sizes, int n_in,
                              void* d_out, int out_size) {
    const float* vertex = (const float*)d_in[0];   // [8,1024,256]
    const float* w_vert = (const float*)d_in[1];   // [256,256]
    const float* attn_w = (const float*)d_in[2];   // [64]
    float* out = (float*)d_out;                    // [8,1024,256]

    dim3 gA(OCOLS / 64, M_TOT / 64);   // (4, 128)
    gemm_g_k<<<gA, 256>>>(vertex, w_vert);
    score_k<<<M_TOT / 8, 256>>>(attn_w);
    prep_k<<<NBH, 1024>>>();
    query_k<<<NBH * 32, 1024>>>(out);
}

// round 3
// speedup vs baseline: 1.2219x; 1.2219x over previous
#include <cuda_runtime.h>
#include <cuda_bf16.h>
#include <cstdint>

// Problem constants
#define B_    8
#define N_    1024
#define FIN   256
#define NH    8
#define ND    32
#define M_TOT (B_ * N_)      // 8192
#define NBH   (B_ * NH)      // 64
#define ROWS  1025
#define OCOLS (NH * ND)      // 256

// ---------------- scratch ----------------
__device__ float g_buf[M_TOT * OCOLS];        // g[m][h*32+d] fp32
__device__ float ssrc_buf[M_TOT * NH];
__device__ float sdst_buf[M_TOT * NH];
__device__ float vsort_buf[NBH * N_];
__device__ float suf1_buf[NBH * ROWS * ND];
__device__ float pre2_buf[NBH * ROWS * ND];
__device__ float c1_buf[NBH * ROWS];
__device__ float c2_buf[NBH * ROWS];
__device__ float4 qscal_buf[M_TOT * NH];      // {E1/den, E2/den, bits(t), 0}

// ---------------- mma.sync helper ----------------
#define MMA_BF16(d, a, b)                                                      \
    asm volatile("mma.sync.aligned.m16n8k16.row.col.f32.bf16.bf16.f32 "        \
        "{%0,%1,%2,%3}, {%4,%5,%6,%7}, {%8,%9}, {%0,%1,%2,%3};"                \
        : "+f"((d)[0]), "+f"((d)[1]), "+f"((d)[2]), "+f"((d)[3])               \
        : "r"((a)[0]), "r"((a)[1]), "r"((a)[2]), "r"((a)[3]),                  \
          "r"((b)[0]), "r"((b)[1]))

// ---------------- kernel 1: g = vertex @ w_vert via HMMA bf16 hi/lo ----------------
// grid (2, 64): blockIdx.x = n-tile (128 cols), blockIdx.y = m-tile (128 rows).
// 256 threads = 8 warps in 2(m) x 4(n); warp tile 64m x 32n; mma m16n8k16.
#define KC 32
#define APAD 8
__global__ __launch_bounds__(256) void gemm_mma_k(const float* __restrict__ A,
                                                  const float* __restrict__ W) {
    __shared__ __align__(16) __nv_bfloat16 Ah[128][KC + APAD];
    __shared__ __align__(16) __nv_bfloat16 Al[128][KC + APAD];
    __shared__ __align__(16) __nv_bfloat16 Bh[128][KC + APAD];
    __shared__ __align__(16) __nv_bfloat16 Bl[128][KC + APAD];

    const int tid = threadIdx.x;
    const int wid = tid >> 5, lane = tid & 31;
    const int wm = wid >> 2, wn = wid & 3;
    const int rowBase = blockIdx.y * 128;
    const int colBase = blockIdx.x * 128;
    const int g = lane >> 2, tg = lane & 3;

    float acc[4][4][4];
#pragma unroll
    for (int mt = 0; mt < 4; mt++)
#pragma unroll
        for (int nt = 0; nt < 4; nt++)
#pragma unroll
            for (int r = 0; r < 4; r++) acc[mt][nt][r] = 0.f;

    for (int k0 = 0; k0 < FIN; k0 += KC) {
        __syncthreads();
        // stage A chunk (128 x 32 fp32), split hi/lo
#pragma unroll
        for (int it = 0; it < 4; it++) {
            int i = tid + it * 256;                 // 0..1023 float4s
            int r = i >> 3, c4 = (i & 7) << 2;      // row, col (float4 granular)
            float4 v = *(const float4*)(A + (size_t)(rowBase + r) * FIN + k0 + c4);
            float xs[4] = {v.x, v.y, v.z, v.w};
#pragma unroll
            for (int c = 0; c < 4; c++) {
                __nv_bfloat16 h = __float2bfloat16(xs[c]);
                Ah[r][c4 + c] = h;
                Al[r][c4 + c] = __float2bfloat16(xs[c] - __bfloat162float(h));
            }
        }
        // stage B chunk: W is [k][n]; store transposed as Bs[n][k], split hi/lo
#pragma unroll
        for (int it = 0; it < 4; it++) {
            int i = tid + it * 256;
            int kr = i >> 5, n4 = (i & 31) << 2;
            float4 v = *(const float4*)(W + (size_t)(k0 + kr) * OCOLS + colBase + n4);
            float xs[4] = {v.x, v.y, v.z, v.w};
#pragma unroll
            for (int c = 0; c < 4; c++) {
                __nv_bfloat16 h = __float2bfloat16(xs[c]);
                Bh[n4 + c][kr] = h;
                Bl[n4 + c][kr] = __float2bfloat16(xs[c] - __bfloat162float(h));
            }
        }
        __syncthreads();

#pragma unroll
        for (int ks = 0; ks < 2; ks++) {
            const int kk = ks << 4;
            uint32_t ah[4][4], al[4][4], bb[4][2];
#pragma unroll
            for (int mt = 0; mt < 4; mt++) {
                int r0 = wm * 64 + mt * 16 + g;
                ah[mt][0] = *(const uint32_t*)&Ah[r0][kk + tg * 2];
                ah[mt][1] = *(const uint32_t*)&Ah[r0 + 8][kk + tg * 2];
                ah[mt][2] = *(const uint32_t*)&Ah[r0][kk + 8 + tg * 2];
                ah[mt][3] = *(const uint32_t*)&Ah[r0 + 8][kk + 8 + tg * 2];
                al[mt][0] = *(const uint32_t*)&Al[r0][kk + tg * 2];
                al[mt][1] = *(const uint32_t*)&Al[r0 + 8][kk + tg * 2];
                al[mt][2] = *(const uint32_t*)&Al[r0][kk + 8 + tg * 2];
                al[mt][3] = *(const uint32_t*)&Al[r0 + 8][kk + 8 + tg * 2];
            }
#pragma unroll
            for (int nt = 0; nt < 4; nt++) {
                int n0 = wn * 32 + nt * 8 + g;
                bb[nt][0] = *(const uint32_t*)&Bh[n0][kk + tg * 2];
                bb[nt][1] = *(const uint32_t*)&Bh[n0][kk + 8 + tg * 2];
            }
#pragma unroll
            for (int mt = 0; mt < 4; mt++)
#pragma unroll
                for (int nt = 0; nt < 4; nt++) {
                    MMA_BF16(acc[mt][nt], ah[mt], bb[nt]);   // hi*hi
                    MMA_BF16(acc[mt][nt], al[mt], bb[nt]);   // lo*hi
                }
#pragma unroll
            for (int nt = 0; nt < 4; nt++) {
                int n0 = wn * 32 + nt * 8 + g;
                bb[nt][0] = *(const uint32_t*)&Bl[n0][kk + tg * 2];
                bb[nt][1] = *(const uint32_t*)&Bl[n0][kk + 8 + tg * 2];
            }
#pragma unroll
            for (int mt = 0; mt < 4; mt++)
#pragma unroll
                for (int nt = 0; nt < 4; nt++)
                    MMA_BF16(acc[mt][nt], ah[mt], bb[nt]);   // hi*lo
        }
    }

    // epilogue
#pragma unroll
    for (int mt = 0; mt < 4; mt++) {
        int r0 = rowBase + wm * 64 + mt * 16 + g;
#pragma unroll
        for (int nt = 0; nt < 4; nt++) {
            int c0 = colBase + wn * 32 + nt * 8 + tg * 2;
            *(float2*)(g_buf + (size_t)r0 * OCOLS + c0) =
                make_float2(acc[mt][nt][0], acc[mt][nt][1]);
            *(float2*)(g_buf + (size_t)(r0 + 8) * OCOLS + c0) =
                make_float2(acc[mt][nt][2], acc[mt][nt][3]);
        }
    }
}

// ---------------- kernel 2: s_src, s_dst ----------------
__global__ __launch_bounds__(256) void score_k(const float* __restrict__ attn_w) {
    int w = threadIdx.x >> 5, lane = threadIdx.x & 31;
    int m = blockIdx.x * 8 + w;
    float ws = attn_w[lane];
    float wd = attn_w[32 + lane];
    const float* gr = g_buf + (size_t)m * OCOLS;
#pragma unroll
    for (int h = 0; h < NH; h++) {
        float gv = gr[h * ND + lane];
        float a = gv * ws, b = gv * wd;
#pragma unroll
        for (int o = 16; o > 0; o >>= 1) {
            a += __shfl_xor_sync(0xffffffffu, a, o);
            b += __shfl_xor_sync(0xffffffffu, b, o);
        }
        if (lane == 0) {
            ssrc_buf[m * NH + h] = a;
            sdst_buf[m * NH + h] = b;
        }
    }
}

// ---------------- kernel 3: sort + prefix/suffix structures ----------------
__device__ __forceinline__ void warp_passes(float& v, int& id, int k, int jmax, int tid) {
    for (int j = jmax; j > 0; j >>= 1) {
        float pv = __shfl_xor_sync(0xffffffffu, v, j);
        int pid = __shfl_xor_sync(0xffffffffu, id, j);
        bool lower = ((tid & j) == 0);
        bool up = ((tid & k) == 0);
        bool keepmin = (lower == up);
        bool sw = keepmin ? (v > pv) : (v < pv);
        if (sw) { v = pv; id = pid; }
    }
}

__global__ __launch_bounds__(1024) void prep_k() {
    __shared__ float sv[1024];
    __shared__ int   sid[1024];
    __shared__ float e1s[1024];
    __shared__ float e2s[1024];
    __shared__ float wt[32], wo[32], wt2[32], wo2[32];
    __shared__ float tot1[32][33];
    __shared__ float tot2[32][33];

    int bh = blockIdx.x;
    int b = bh >> 3, h = bh & 7;
    int tid = threadIdx.x;
    int w = tid >> 5, lane = tid & 31;

    float rv = sdst_buf[(size_t)(b * N_ + tid) * NH + h];
    int rid = tid;

#pragma unroll
    for (int k = 2; k <= 32; k <<= 1) warp_passes(rv, rid, k, k >> 1, tid);
    sv[tid] = rv; sid[tid] = rid;
    __syncthreads();
    for (int k = 64; k <= 1024; k <<= 1) {
        for (int j = k >> 1; j >= 32; j >>= 1) {
            int ixj = tid ^ j;
            if (ixj > tid) {
                bool up = ((tid & k) == 0);
                float a = sv[tid], c = sv[ixj];
                bool sw = up ? (a > c) : (a < c);
                if (sw) {
                    sv[tid] = c; sv[ixj] = a;
                    int t_ = sid[tid]; sid[tid] = sid[ixj]; sid[ixj] = t_;
                }
            }
            __syncthreads();
        }
        rv = sv[tid]; rid = sid[tid];
        warp_passes(rv, rid, k, 16, tid);
        sv[tid] = rv; sid[tid] = rid;
        __syncthreads();
    }

    vsort_buf[(size_t)bh * N_ + tid] = rv;
    float x1 = __expf(rv);
    float x2 = __expf(0.2f * rv);
    e1s[tid] = x1; e2s[tid] = x2;

    float s2 = x2;
#pragma unroll
    for (int o = 1; o < 32; o <<= 1) {
        float y = __shfl_up_sync(0xffffffffu, s2, o);
        if (lane >= o) s2 += y;
    }
    if (lane == 31) wt2[w] = s2;
    float s1 = x1;
#pragma unroll
    for (int o = 1; o < 32; o <<= 1) {
        float y = __shfl_down_sync(0xffffffffu, s1, o);
        if (lane + o < 32) s1 += y;
    }
    if (lane == 0) wt[w] = s1;
    __syncthreads();
    if (w == 0) {
        float t = wt[lane];
        float ts = t;
#pragma unroll
        for (int o = 1; o < 32; o <<= 1) {
            float y = __shfl_down_sync(0xffffffffu, ts, o);
            if (lane + o < 32) ts += y;
        }
        wo[lane] = ts - t;
        float t2 = wt2[lane];
        float ps = t2;
#pragma unroll
        for (int o = 1; o < 32; o <<= 1) {
            float y = __shfl_up_sync(0xffffffffu, ps, o);
            if (lane >= o) ps += y;
        }
        wo2[lane] = ps - t2;
    }
    __syncthreads();
    c1_buf[(size_t)bh * ROWS + tid] = s1 + wo[w];
    c2_buf[(size_t)bh * ROWS + tid + 1] = s2 + wo2[w];
    if (tid == 0) {
        c1_buf[(size_t)bh * ROWS + 1024] = 0.f;
        c2_buf[(size_t)bh * ROWS] = 0.f;
    }

    const float* gb = g_buf + (size_t)b * N_ * OCOLS + h * ND;

    float t1 = 0.f, t2v = 0.f;
    for (int kk = 0; kk < 32; kk++) {
        int k = (w << 5) + kk;
        int j = sid[k];
        float gv = gb[(size_t)j * OCOLS + lane];
        t1 += e1s[k] * gv;
        t2v += e2s[k] * gv;
    }
    tot1[w][lane] = t1;
    tot2[w][lane] = t2v;
    __syncthreads();
    {
        float a1 = tot1[lane][w];
        float a2 = tot2[lane][w];
        float inc1 = a1;
#pragma unroll
        for (int o = 1; o < 32; o <<= 1) {
            float y = __shfl_down_sync(0xffffffffu, inc1, o);
            if (lane + o < 32) inc1 += y;
        }
        float inc2 = a2;
#pragma unroll
        for (int o = 1; o < 32; o <<= 1) {
            float y = __shfl_up_sync(0xffffffffu, inc2, o);
            if (lane >= o) inc2 += y;
        }
        tot1[lane][w] = inc1 - a1;
        tot2[lane][w] = inc2 - a2;
    }
    __syncthreads();

    {
        float r2 = tot2[w][lane];
        float* P2 = pre2_buf + (size_t)bh * ROWS * ND;
        for (int kk = 0; kk < 32; kk++) {
            int k = (w << 5) + kk;
            int j = sid[k];
            float gv = gb[(size_t)j * OCOLS + lane];
            r2 += e2s[k] * gv;
            P2[(size_t)(k + 1) * ND + lane] = r2;
        }
        if (tid < 32) P2[lane] = 0.f;
    }
    {
        float r1 = tot1[w][lane];
        float* S1 = suf1_buf + (size_t)bh * ROWS * ND;
        for (int kk = 31; kk >= 0; kk--) {
            int k = (w << 5) + kk;
            int j = sid[k];
            float gv = gb[(size_t)j * OCOLS + lane];
            r1 += e1s[k] * gv;
            S1[(size_t)k * ND + lane] = r1;
        }
        if (tid < 32) S1[(size_t)1024 * ND + lane] = 0.f;
    }
}

// ---------------- kernel 4a: per-query scalars ----------------
__global__ __launch_bounds__(256) void qscal_k() {
    int q = blockIdx.x * 256 + threadIdx.x;    // q = m*8 + h
    int m = q >> 3, h = q & 7;
    int bh = (m >> 10) * NH + h;
    float src = ssrc_buf[q];
    float th = -src;
    const float* vs = vsort_buf + (size_t)bh * N_;

    int lo = 0, hi = 1024;
#pragma unroll
    for (int s = 0; s < 10; s++) {
        int mid = (lo + hi) >> 1;
        if (vs[mid] < th) lo = mid + 1; else hi = mid;
    }
    int t = lo;

    float vmax = vs[1023];
    float etop = src + vmax;
    float mM = (etop >= 0.f) ? etop : 0.2f * etop;
    float E1 = (t < 1024) ? __expf(src - mM) : 0.f;
    float E2 = (t > 0) ? __expf(0.2f * src - mM) : 0.f;

    float cs = c1_buf[(size_t)bh * ROWS + t];
    float cp = c2_buf[(size_t)bh * ROWS + t];
    float rden = 1.f / (E1 * cs + E2 * cp);
    qscal_buf[q] = make_float4(E1 * rden, E2 * rden, __int_as_float(t), 0.f);
}

// ---------------- kernel 4b: output ----------------
__global__ __launch_bounds__(256) void out_k(float* __restrict__ out) {
    int g = blockIdx.x * 256 + threadIdx.x;    // 2M elems
    int m = g >> 8, c = g & 255;
    int h = c >> 5, d = c & 31;
    float4 s = qscal_buf[m * NH + h];
    int t = __float_as_int(s.z);
    int bh = (m >> 10) * NH + h;
    size_t base = ((size_t)bh * ROWS + t) * ND + d;
    out[g] = s.x * suf1_buf[base] + s.y * pre2_buf[base];
}

// ---------------- launcher ----------------
extern "C" void kernel_launch(void* const* d_in, const int* in_sizes, int n_in,
                              void* d_out, int out_size) {
    const float* vertex = (const float*)d_in[0];
    const float* w_vert = (const float*)d_in[1];
    const float* attn_w = (const float*)d_in[2];
    float* out = (float*)d_out;

    dim3 gG(2, 64);
    gemm_mma_k<<<gG, 256>>>(vertex, w_vert);
    score_k<<<M_TOT / 8, 256>>>(attn_w);
    prep_k<<<NBH, 1024>>>();
    qscal_k<<<M_TOT * NH / 256, 256>>>();
    out_k<<<M_TOT * OCOLS / 256, 256>>>(out);
}